// round 1
// baseline (speedup 1.0000x reference)
#include <cuda_runtime.h>
#include <cstdint>

#define BB 4
#define NN 8192
#define KK 16
#define DD 128
#define GG 32
#define MM (BB*NN)          // 32768 rows
#define BN_EPS 1e-5f

// ---------------- scratch (device globals; no allocation) ----------------
__device__ float g_h[(size_t)MM * DD];        // projected features, 16 MB
__device__ float g_psum[128][DD];             // stage-1 partial sums
__device__ float g_psum2[128][DD];            // stage-1 partial sums of squares
__device__ float g_scale[DD];                 // fused BN scale
__device__ float g_shift[DD];                 // fused BN shift

// ---------------- kernel 1: h = X * W^T  (M=32768, K=128, N=128) ----------
// Block: 256 thr, tile 64 rows x 128 cols, thread tile 4x8, K chunk 32.
// Smem transposed ([k][row]) so inner loads are float4.
__global__ void __launch_bounds__(256) gemm_kernel(const float* __restrict__ X,
                                                   const float* __restrict__ W,
                                                   float* __restrict__ H) {
    __shared__ float Xs[32][68];    // [k][row], pad 68 (68*4 % 16 == 0)
    __shared__ float Ws[32][136];   // [k][d],   pad 136

    const int tid = threadIdx.x;
    const int ty = tid >> 4;        // 0..15 -> 4 rows each
    const int tx = tid & 15;        // 0..15 -> 8 cols each
    const int m0 = blockIdx.x * 64;

    float acc[4][8];
#pragma unroll
    for (int i = 0; i < 4; i++)
#pragma unroll
        for (int j = 0; j < 8; j++) acc[i][j] = 0.f;

    for (int kc = 0; kc < DD; kc += 32) {
        // load X tile 64x32 (512 float4), 2 per thread
#pragma unroll
        for (int i = 0; i < 2; i++) {
            int q = tid + i * 256;          // 0..511
            int row = q >> 3;               // 0..63
            int cq  = q & 7;                // 0..7 (float4 within 32 k's)
            float4 v = *(const float4*)(X + (size_t)(m0 + row) * DD + kc + cq * 4);
            Xs[cq * 4 + 0][row] = v.x;
            Xs[cq * 4 + 1][row] = v.y;
            Xs[cq * 4 + 2][row] = v.z;
            Xs[cq * 4 + 3][row] = v.w;
        }
        // load W tile 128x32 (1024 float4), 4 per thread
#pragma unroll
        for (int i = 0; i < 4; i++) {
            int q = tid + i * 256;          // 0..1023
            int d  = q >> 3;                // 0..127
            int cq = q & 7;
            float4 v = *(const float4*)(W + (size_t)d * DD + kc + cq * 4);
            Ws[cq * 4 + 0][d] = v.x;
            Ws[cq * 4 + 1][d] = v.y;
            Ws[cq * 4 + 2][d] = v.z;
            Ws[cq * 4 + 3][d] = v.w;
        }
        __syncthreads();

#pragma unroll
        for (int kk = 0; kk < 32; kk++) {
            float4 a  = *(const float4*)&Xs[kk][ty * 4];
            float4 b0 = *(const float4*)&Ws[kk][tx * 8];
            float4 b1 = *(const float4*)&Ws[kk][tx * 8 + 4];
            const float av[4] = {a.x, a.y, a.z, a.w};
            const float bv[8] = {b0.x, b0.y, b0.z, b0.w, b1.x, b1.y, b1.z, b1.w};
#pragma unroll
            for (int i = 0; i < 4; i++)
#pragma unroll
                for (int j = 0; j < 8; j++)
                    acc[i][j] = fmaf(av[i], bv[j], acc[i][j]);
        }
        __syncthreads();
    }

#pragma unroll
    for (int i = 0; i < 4; i++) {
        float* dst = H + (size_t)(m0 + ty * 4 + i) * DD + tx * 8;
        *(float4*)(dst)     = make_float4(acc[i][0], acc[i][1], acc[i][2], acc[i][3]);
        *(float4*)(dst + 4) = make_float4(acc[i][4], acc[i][5], acc[i][6], acc[i][7]);
    }
}

// ---------------- kernel 2: KNN gather + spatial encoding + max -----------
// One warp per point. Lane g handles channel group [4g, 4g+4).
__global__ void __launch_bounds__(256) gather_kernel(const float* __restrict__ H,
                                                     const float* __restrict__ xyz,
                                                     const int* __restrict__ knn,
                                                     const float* __restrict__ coor,
                                                     const float* __restrict__ scale,
                                                     float* __restrict__ agg) {
    const int warp = (blockIdx.x * blockDim.x + threadIdx.x) >> 5;
    const int lane = threadIdx.x & 31;
    if (warp >= MM) return;

    const int b = warp >> 13;          // warp / 8192
    const int base = b << 13;          // b*N

    // per-lane encoding weights (lane == group)
    const float wx = coor[3 * lane + 0];
    const float wy = coor[3 * lane + 1];
    const float wz = coor[3 * lane + 2];
    const float sv = scale[lane];
    const float ws = sv * sv;

    const float* cptr = xyz + (size_t)warp * 3;
    const float cx = cptr[0], cy = cptr[1], cz = cptr[2];

    const int nb = knn[(size_t)warp * KK + (lane & 15)];

    float4 acc = make_float4(-3.402823466e38f, -3.402823466e38f,
                             -3.402823466e38f, -3.402823466e38f);

#pragma unroll
    for (int k = 0; k < KK; k++) {
        const int idx = __shfl_sync(0xffffffffu, nb, k);
        const int row = base + idx;
        const float* nx = xyz + (size_t)row * 3;
        const float rx = nx[0] - cx;
        const float ry = nx[1] - cy;
        const float rz = nx[2] - cz;
        const float r2 = fmaf(rx, rx, fmaf(ry, ry, rz * rz));
        const float e  = fmaf(rx, wx, fmaf(ry, wy, fmaf(rz, wz, r2 * ws)));
        const float4 hv = *(const float4*)(H + (size_t)row * DD + lane * 4);
        acc.x = fmaxf(acc.x, hv.x + e);
        acc.y = fmaxf(acc.y, hv.y + e);
        acc.z = fmaxf(acc.z, hv.z + e);
        acc.w = fmaxf(acc.w, hv.w + e);
    }

    *(float4*)(agg + (size_t)warp * DD + lane * 4) = acc;
}

// ---------------- kernel 3: BN stats, stage 1 (deterministic) -------------
// 128 blocks x 256 thr. Block b reduces rows [256b, 256b+256).
__global__ void __launch_bounds__(256) stats1_kernel(const float* __restrict__ agg) {
    __shared__ float sh[256], sh2[256];
    const int c    = threadIdx.x & 127;
    const int half = threadIdx.x >> 7;
    const int r0   = blockIdx.x * 256;

    float s = 0.f, s2 = 0.f;
    for (int i = half; i < 256; i += 2) {
        const float v = agg[(size_t)(r0 + i) * DD + c];
        s  += v;
        s2 = fmaf(v, v, s2);
    }
    sh[threadIdx.x]  = s;
    sh2[threadIdx.x] = s2;
    __syncthreads();
    if (half == 0) {
        g_psum [blockIdx.x][c] = sh[c]  + sh[c + 128];
        g_psum2[blockIdx.x][c] = sh2[c] + sh2[c + 128];
    }
}

// ---------------- kernel 4: BN stats, stage 2 -----------------------------
__global__ void stats2_kernel(const float* __restrict__ bn_w,
                              const float* __restrict__ bn_b) {
    const int c = threadIdx.x;   // 128 threads
    float s = 0.f, s2 = 0.f;
#pragma unroll 4
    for (int i = 0; i < 128; i++) {
        s  += g_psum[i][c];
        s2 += g_psum2[i][c];
    }
    const float inv_m = 1.f / (float)MM;
    const float mean = s * inv_m;
    const float var  = fmaf(-mean, mean, s2 * inv_m);
    const float a = bn_w[c] * rsqrtf(var + BN_EPS);
    g_scale[c] = a;
    g_shift[c] = fmaf(-mean, a, bn_b[c]);
}

// ---------------- kernel 5: in-place normalize ----------------------------
__global__ void __launch_bounds__(256) norm_kernel(float* __restrict__ out) {
    __shared__ float sa[DD], sb[DD];
    if (threadIdx.x < DD) {
        sa[threadIdx.x] = g_scale[threadIdx.x];
        sb[threadIdx.x] = g_shift[threadIdx.x];
    }
    __syncthreads();

    const int total = MM * (DD / 4);   // float4 elements
    for (int t = blockIdx.x * blockDim.x + threadIdx.x; t < total;
         t += gridDim.x * blockDim.x) {
        float4 v = ((float4*)out)[t];
        const int c0 = (t & 31) * 4;
        v.x = fmaf(v.x, sa[c0 + 0], sb[c0 + 0]);
        v.y = fmaf(v.y, sa[c0 + 1], sb[c0 + 1]);
        v.z = fmaf(v.z, sa[c0 + 2], sb[c0 + 2]);
        v.w = fmaf(v.w, sa[c0 + 3], sb[c0 + 3]);
        ((float4*)out)[t] = v;
    }
}

// ---------------- launch ---------------------------------------------------
extern "C" void kernel_launch(void* const* d_in, const int* in_sizes, int n_in,
                              void* d_out, int out_size) {
    const float* x      = (const float*)d_in[0];
    const float* xyz    = (const float*)d_in[1];
    const int*   knn    = (const int*)  d_in[2];
    const float* proj_w = (const float*)d_in[3];
    const float* coor   = (const float*)d_in[4];
    const float* scale  = (const float*)d_in[5];
    const float* bn_w   = (const float*)d_in[6];
    const float* bn_b   = (const float*)d_in[7];
    float* out = (float*)d_out;

    float* h;
    cudaGetSymbolAddress((void**)&h, g_h);

    gemm_kernel<<<MM / 64, 256>>>(x, proj_w, h);
    gather_kernel<<<MM / 8, 256>>>(h, xyz, knn, coor, scale, out);
    stats1_kernel<<<128, 256>>>(out);
    stats2_kernel<<<1, 128>>>(bn_w, bn_b);
    norm_kernel<<<1024, 256>>>(out);
}

// round 2
// speedup vs baseline: 1.4327x; 1.4327x over previous
#include <cuda_runtime.h>
#include <cstdint>

#define BB 4
#define NN 8192
#define KK 16
#define DD 128
#define GG 32
#define MM (BB*NN)          // 32768 rows
#define BN_EPS 1e-5f

// ---------------- scratch (device globals; no allocation) ----------------
__device__ float g_h[(size_t)MM * DD];        // projected features, 16 MB
__device__ float g_psum[128][DD];             // stage-1 partial sums
__device__ float g_psum2[128][DD];            // stage-1 partial sums of squares
__device__ float g_scale[DD];                 // fused BN scale
__device__ float g_shift[DD];                 // fused BN shift

// ---------------- kernel 1: h = X * W^T  (M=32768, K=128, N=128) ----------
// Block: 256 thr (16x16), tile 128x128, thread tile 8x8 (split 4+4 halves
// so LDS.128 phases are conflict-free), K chunk 16.
__global__ void __launch_bounds__(256) gemm_kernel(const float* __restrict__ X,
                                                   const float* __restrict__ W,
                                                   float* __restrict__ H) {
    __shared__ float Xs[16][132];   // [k][m], pad 132 (multiple of 4)
    __shared__ float Ws[16][132];   // [k][d]

    const int tid = threadIdx.x;
    const int ty = tid >> 4;        // 0..15
    const int tx = tid & 15;        // 0..15
    const int m0 = blockIdx.x * 128;

    float acc[8][8];
#pragma unroll
    for (int i = 0; i < 8; i++)
#pragma unroll
        for (int j = 0; j < 8; j++) acc[i][j] = 0.f;

    for (int kc = 0; kc < DD; kc += 16) {
        // X tile 128x16 = 512 float4, 2 per thread
#pragma unroll
        for (int i = 0; i < 2; i++) {
            int q = tid + i * 256;          // 0..511
            int row = q >> 2;               // 0..127
            int kq  = q & 3;                // float4 index within 16 k's
            float4 v = *(const float4*)(X + (size_t)(m0 + row) * DD + kc + kq * 4);
            Xs[kq * 4 + 0][row] = v.x;
            Xs[kq * 4 + 1][row] = v.y;
            Xs[kq * 4 + 2][row] = v.z;
            Xs[kq * 4 + 3][row] = v.w;
        }
        // W tile 128x16 = 512 float4, 2 per thread
#pragma unroll
        for (int i = 0; i < 2; i++) {
            int q = tid + i * 256;
            int d  = q >> 2;
            int kq = q & 3;
            float4 v = *(const float4*)(W + (size_t)d * DD + kc + kq * 4);
            Ws[kq * 4 + 0][d] = v.x;
            Ws[kq * 4 + 1][d] = v.y;
            Ws[kq * 4 + 2][d] = v.z;
            Ws[kq * 4 + 3][d] = v.w;
        }
        __syncthreads();

#pragma unroll
        for (int kk = 0; kk < 16; kk++) {
            float4 a0 = *(const float4*)&Xs[kk][ty * 4];
            float4 a1 = *(const float4*)&Xs[kk][64 + ty * 4];
            float4 b0 = *(const float4*)&Ws[kk][tx * 4];
            float4 b1 = *(const float4*)&Ws[kk][64 + tx * 4];
            const float av[8] = {a0.x, a0.y, a0.z, a0.w, a1.x, a1.y, a1.z, a1.w};
            const float bv[8] = {b0.x, b0.y, b0.z, b0.w, b1.x, b1.y, b1.z, b1.w};
#pragma unroll
            for (int i = 0; i < 8; i++)
#pragma unroll
                for (int j = 0; j < 8; j++)
                    acc[i][j] = fmaf(av[i], bv[j], acc[i][j]);
        }
        __syncthreads();
    }

    // rows: ty*4+i (i<4) and 64+ty*4+(i-4); cols: tx*4.. and 64+tx*4..
#pragma unroll
    for (int i = 0; i < 8; i++) {
        const int row = m0 + ((i < 4) ? (ty * 4 + i) : (64 + ty * 4 + i - 4));
        float* dst = H + (size_t)row * DD;
        *(float4*)(dst + tx * 4)      = make_float4(acc[i][0], acc[i][1], acc[i][2], acc[i][3]);
        *(float4*)(dst + 64 + tx * 4) = make_float4(acc[i][4], acc[i][5], acc[i][6], acc[i][7]);
    }
}

// ---------------- kernel 2: KNN gather + spatial encoding + max -----------
// One warp per point. Lane g handles channel group [4g, 4g+4).
__global__ void __launch_bounds__(256) gather_kernel(const float* __restrict__ H,
                                                     const float* __restrict__ xyz,
                                                     const int* __restrict__ knn,
                                                     const float* __restrict__ coor,
                                                     const float* __restrict__ scale,
                                                     float* __restrict__ agg) {
    const int warp = (blockIdx.x * blockDim.x + threadIdx.x) >> 5;
    const int lane = threadIdx.x & 31;
    if (warp >= MM) return;

    const int b = warp >> 13;          // warp / 8192
    const int base = b << 13;          // b*N

    // per-lane encoding weights (lane == group)
    const float wx = coor[3 * lane + 0];
    const float wy = coor[3 * lane + 1];
    const float wz = coor[3 * lane + 2];
    const float sv = scale[lane];
    const float ws = sv * sv;

    const float* cptr = xyz + (size_t)warp * 3;
    const float cx = cptr[0], cy = cptr[1], cz = cptr[2];

    const int nb = knn[(size_t)warp * KK + (lane & 15)];

    float4 acc = make_float4(-3.402823466e38f, -3.402823466e38f,
                             -3.402823466e38f, -3.402823466e38f);

#pragma unroll
    for (int k = 0; k < KK; k++) {
        const int idx = __shfl_sync(0xffffffffu, nb, k);
        const int row = base + idx;
        const float* nx = xyz + (size_t)row * 3;
        const float rx = nx[0] - cx;
        const float ry = nx[1] - cy;
        const float rz = nx[2] - cz;
        const float r2 = fmaf(rx, rx, fmaf(ry, ry, rz * rz));
        const float e  = fmaf(rx, wx, fmaf(ry, wy, fmaf(rz, wz, r2 * ws)));
        const float4 hv = *(const float4*)(H + (size_t)row * DD + lane * 4);
        acc.x = fmaxf(acc.x, hv.x + e);
        acc.y = fmaxf(acc.y, hv.y + e);
        acc.z = fmaxf(acc.z, hv.z + e);
        acc.w = fmaxf(acc.w, hv.w + e);
    }

    *(float4*)(agg + (size_t)warp * DD + lane * 4) = acc;
}

// ---------------- kernel 3: BN stats, stage 1 (deterministic) -------------
// 128 blocks x 256 thr. Block b reduces rows [256b, 256b+256).
__global__ void __launch_bounds__(256) stats1_kernel(const float* __restrict__ agg) {
    __shared__ float sh[256], sh2[256];
    const int c    = threadIdx.x & 127;
    const int half = threadIdx.x >> 7;
    const int r0   = blockIdx.x * 256;

    float s = 0.f, s2 = 0.f;
    for (int i = half; i < 256; i += 2) {
        const float v = agg[(size_t)(r0 + i) * DD + c];
        s  += v;
        s2 = fmaf(v, v, s2);
    }
    sh[threadIdx.x]  = s;
    sh2[threadIdx.x] = s2;
    __syncthreads();
    if (half == 0) {
        g_psum [blockIdx.x][c] = sh[c]  + sh[c + 128];
        g_psum2[blockIdx.x][c] = sh2[c] + sh2[c + 128];
    }
}

// ---------------- kernel 4: BN stats, stage 2 (parallelized) --------------
// 512 threads: channel c = tid&127, chunk = tid>>7 sums 32 of 128 partials.
__global__ void __launch_bounds__(512) stats2_kernel(const float* __restrict__ bn_w,
                                                     const float* __restrict__ bn_b) {
    __shared__ float ss[4][DD], ss2[4][DD];
    const int c     = threadIdx.x & 127;
    const int chunk = threadIdx.x >> 7;   // 0..3

    float s = 0.f, s2 = 0.f;
#pragma unroll
    for (int i = 0; i < 32; i++) {
        const int p = chunk * 32 + i;
        s  += g_psum[p][c];
        s2 += g_psum2[p][c];
    }
    ss[chunk][c]  = s;
    ss2[chunk][c] = s2;
    __syncthreads();

    if (chunk == 0) {
        s  = ss[0][c]  + ss[1][c]  + ss[2][c]  + ss[3][c];
        s2 = ss2[0][c] + ss2[1][c] + ss2[2][c] + ss2[3][c];
        const float inv_m = 1.f / (float)MM;
        const float mean = s * inv_m;
        const float var  = fmaf(-mean, mean, s2 * inv_m);
        const float a = bn_w[c] * rsqrtf(var + BN_EPS);
        g_scale[c] = a;
        g_shift[c] = fmaf(-mean, a, bn_b[c]);
    }
}

// ---------------- kernel 5: in-place normalize ----------------------------
__global__ void __launch_bounds__(256) norm_kernel(float* __restrict__ out) {
    __shared__ float sa[DD], sb[DD];
    if (threadIdx.x < DD) {
        sa[threadIdx.x] = g_scale[threadIdx.x];
        sb[threadIdx.x] = g_shift[threadIdx.x];
    }
    __syncthreads();

    const int total = MM * (DD / 4);   // float4 elements
    for (int t = blockIdx.x * blockDim.x + threadIdx.x; t < total;
         t += gridDim.x * blockDim.x) {
        float4 v = ((float4*)out)[t];
        const int c0 = (t & 31) * 4;
        v.x = fmaf(v.x, sa[c0 + 0], sb[c0 + 0]);
        v.y = fmaf(v.y, sa[c0 + 1], sb[c0 + 1]);
        v.z = fmaf(v.z, sa[c0 + 2], sb[c0 + 2]);
        v.w = fmaf(v.w, sa[c0 + 3], sb[c0 + 3]);
        ((float4*)out)[t] = v;
    }
}

// ---------------- launch ---------------------------------------------------
extern "C" void kernel_launch(void* const* d_in, const int* in_sizes, int n_in,
                              void* d_out, int out_size) {
    const float* x      = (const float*)d_in[0];
    const float* xyz    = (const float*)d_in[1];
    const int*   knn    = (const int*)  d_in[2];
    const float* proj_w = (const float*)d_in[3];
    const float* coor   = (const float*)d_in[4];
    const float* scale  = (const float*)d_in[5];
    const float* bn_w   = (const float*)d_in[6];
    const float* bn_b   = (const float*)d_in[7];
    float* out = (float*)d_out;

    float* h;
    cudaGetSymbolAddress((void**)&h, g_h);

    gemm_kernel<<<MM / 128, 256>>>(x, proj_w, h);
    gather_kernel<<<MM / 8, 256>>>(h, xyz, knn, coor, scale, out);
    stats1_kernel<<<128, 256>>>(out);
    stats2_kernel<<<1, 512>>>(bn_w, bn_b);
    norm_kernel<<<1024, 256>>>(out);
}

// round 3
// speedup vs baseline: 1.4661x; 1.0233x over previous
#include <cuda_runtime.h>
#include <cstdint>

#define BB 4
#define NN 8192
#define KK 16
#define DD 128
#define GG 32
#define MM (BB*NN)          // 32768 rows
#define BN_EPS 1e-5f

#define NPART 4096          // gather blocks = stats partials

// ---------------- scratch (device globals; no allocation) ----------------
__device__ float g_h[(size_t)MM * DD];        // projected features, 16 MB
__device__ float g_psum [NPART][DD];          // per-gather-block partial sums
__device__ float g_psum2[NPART][DD];          // per-gather-block partial sumsq
__device__ float g_scale[DD];                 // fused BN scale
__device__ float g_shift[DD];                 // fused BN shift

// ---------------- tf32 helpers --------------------------------------------
__device__ __forceinline__ float tf32_rna(float v) {
    uint32_t u;
    asm("cvt.rna.tf32.f32 %0, %1;" : "=r"(u) : "f"(v));
    return __uint_as_float(u);
}

__device__ __forceinline__ void mma_tf32(float c[4],
                                         uint32_t a0, uint32_t a1, uint32_t a2, uint32_t a3,
                                         uint32_t b0, uint32_t b1) {
    asm volatile(
        "mma.sync.aligned.m16n8k8.row.col.f32.tf32.tf32.f32 "
        "{%0,%1,%2,%3}, {%4,%5,%6,%7}, {%8,%9}, {%0,%1,%2,%3};"
        : "+f"(c[0]), "+f"(c[1]), "+f"(c[2]), "+f"(c[3])
        : "r"(a0), "r"(a1), "r"(a2), "r"(a3), "r"(b0), "r"(b1));
}

// ---------------- kernel 1: H = X * W^T via 3xTF32 tensor cores ----------
// Block 256 thr (8 warps, 4x2). Block tile 128(M) x 128(N), warp tile 32x64.
// K chunk 16 (2 k8 steps). Smem row stride 20 floats -> conflict-free frags.
#define BK 16
#define XS_STRIDE 20
__global__ void __launch_bounds__(256) gemm_kernel(const float* __restrict__ X,
                                                   const float* __restrict__ W,
                                                   float* __restrict__ H) {
    __shared__ float Xs_hi[128 * XS_STRIDE];
    __shared__ float Xs_lo[128 * XS_STRIDE];
    __shared__ float Ws_hi[128 * XS_STRIDE];
    __shared__ float Ws_lo[128 * XS_STRIDE];

    const int tid  = threadIdx.x;
    const int warp = tid >> 5;
    const int lane = tid & 31;
    const int wm   = warp >> 1;          // 0..3 -> M offset wm*32
    const int wn   = warp & 1;           // 0..1 -> N offset wn*64
    const int m0   = blockIdx.x * 128;
    const int gr   = lane >> 2;          // groupID 0..7
    const int gc   = lane & 3;           // thread-in-group 0..3

    float c[2][8][4];
#pragma unroll
    for (int i = 0; i < 2; i++)
#pragma unroll
        for (int j = 0; j < 8; j++)
#pragma unroll
            for (int t = 0; t < 4; t++) c[i][j][t] = 0.f;

    for (int kc = 0; kc < DD; kc += BK) {
        // load + split X tile 128x16 (512 float4, 2/thread) and W tile same
#pragma unroll
        for (int i = 0; i < 2; i++) {
            int q   = tid + i * 256;     // 0..511
            int row = q >> 2;            // 0..127
            int cq  = q & 3;             // float4 within 16 k's
            float4 v = *(const float4*)(X + (size_t)(m0 + row) * DD + kc + cq * 4);
            float4 hi, lo;
            hi.x = tf32_rna(v.x); lo.x = tf32_rna(v.x - hi.x);
            hi.y = tf32_rna(v.y); lo.y = tf32_rna(v.y - hi.y);
            hi.z = tf32_rna(v.z); lo.z = tf32_rna(v.z - hi.z);
            hi.w = tf32_rna(v.w); lo.w = tf32_rna(v.w - hi.w);
            *(float4*)&Xs_hi[row * XS_STRIDE + cq * 4] = hi;
            *(float4*)&Xs_lo[row * XS_STRIDE + cq * 4] = lo;

            float4 wv = *(const float4*)(W + (size_t)row * DD + kc + cq * 4);
            float4 whi, wlo;
            whi.x = tf32_rna(wv.x); wlo.x = tf32_rna(wv.x - whi.x);
            whi.y = tf32_rna(wv.y); wlo.y = tf32_rna(wv.y - whi.y);
            whi.z = tf32_rna(wv.z); wlo.z = tf32_rna(wv.z - whi.z);
            whi.w = tf32_rna(wv.w); wlo.w = tf32_rna(wv.w - whi.w);
            *(float4*)&Ws_hi[row * XS_STRIDE + cq * 4] = whi;
            *(float4*)&Ws_lo[row * XS_STRIDE + cq * 4] = wlo;
        }
        __syncthreads();

#pragma unroll
        for (int k8 = 0; k8 < BK / 8; k8++) {
            const int k0 = k8 * 8;
            // A fragments: 2 m16 atoms
            uint32_t ahi[2][4], alo[2][4];
#pragma unroll
            for (int am = 0; am < 2; am++) {
                const int rb = (wm * 32 + am * 16 + gr) * XS_STRIDE + k0 + gc;
                ahi[am][0] = __float_as_uint(Xs_hi[rb]);
                ahi[am][1] = __float_as_uint(Xs_hi[rb + 8 * XS_STRIDE]);
                ahi[am][2] = __float_as_uint(Xs_hi[rb + 4]);
                ahi[am][3] = __float_as_uint(Xs_hi[rb + 8 * XS_STRIDE + 4]);
                alo[am][0] = __float_as_uint(Xs_lo[rb]);
                alo[am][1] = __float_as_uint(Xs_lo[rb + 8 * XS_STRIDE]);
                alo[am][2] = __float_as_uint(Xs_lo[rb + 4]);
                alo[am][3] = __float_as_uint(Xs_lo[rb + 8 * XS_STRIDE + 4]);
            }
#pragma unroll
            for (int an = 0; an < 8; an++) {
                const int nb = (wn * 64 + an * 8 + gr) * XS_STRIDE + k0 + gc;
                uint32_t bhi0 = __float_as_uint(Ws_hi[nb]);
                uint32_t bhi1 = __float_as_uint(Ws_hi[nb + 4]);
                uint32_t blo0 = __float_as_uint(Ws_lo[nb]);
                uint32_t blo1 = __float_as_uint(Ws_lo[nb + 4]);
#pragma unroll
                for (int am = 0; am < 2; am++) {
                    mma_tf32(c[am][an], ahi[am][0], ahi[am][1], ahi[am][2], ahi[am][3], bhi0, bhi1);
                    mma_tf32(c[am][an], ahi[am][0], ahi[am][1], ahi[am][2], ahi[am][3], blo0, blo1);
                    mma_tf32(c[am][an], alo[am][0], alo[am][1], alo[am][2], alo[am][3], bhi0, bhi1);
                }
            }
        }
        __syncthreads();
    }

    // epilogue: c[am][an][t] -> H
#pragma unroll
    for (int am = 0; am < 2; am++) {
        const int row = m0 + wm * 32 + am * 16 + gr;
#pragma unroll
        for (int an = 0; an < 8; an++) {
            const int col = wn * 64 + an * 8 + 2 * gc;
            *(float2*)(H + (size_t)row * DD + col)       = make_float2(c[am][an][0], c[am][an][1]);
            *(float2*)(H + (size_t)(row + 8) * DD + col) = make_float2(c[am][an][2], c[am][an][3]);
        }
    }
}

// ---------------- kernel 2: gather + encoding + max + stats partials ------
// One warp per point, 8 points/block. Lane g owns channels [4g,4g+4).
__global__ void __launch_bounds__(256) gather_kernel(const float* __restrict__ H,
                                                     const float* __restrict__ xyz,
                                                     const int* __restrict__ knn,
                                                     const float* __restrict__ coor,
                                                     const float* __restrict__ scale,
                                                     float* __restrict__ agg) {
    __shared__ float sh_s[8][132];
    __shared__ float sh_q[8][132];

    const int warp = (blockIdx.x * blockDim.x + threadIdx.x) >> 5;
    const int wloc = threadIdx.x >> 5;
    const int lane = threadIdx.x & 31;

    const int b = warp >> 13;          // warp / 8192
    const int base = b << 13;          // b*N

    const float wx = coor[3 * lane + 0];
    const float wy = coor[3 * lane + 1];
    const float wz = coor[3 * lane + 2];
    const float sv = scale[lane];
    const float ws = sv * sv;

    const float* cptr = xyz + (size_t)warp * 3;
    const float cx = cptr[0], cy = cptr[1], cz = cptr[2];

    const int nb = knn[(size_t)warp * KK + (lane & 15)];

    float4 acc = make_float4(-3.402823466e38f, -3.402823466e38f,
                             -3.402823466e38f, -3.402823466e38f);

#pragma unroll
    for (int k = 0; k < KK; k++) {
        const int idx = __shfl_sync(0xffffffffu, nb, k);
        const int row = base + idx;
        const float* nx = xyz + (size_t)row * 3;
        const float rx = nx[0] - cx;
        const float ry = nx[1] - cy;
        const float rz = nx[2] - cz;
        const float r2 = fmaf(rx, rx, fmaf(ry, ry, rz * rz));
        const float e  = fmaf(rx, wx, fmaf(ry, wy, fmaf(rz, wz, r2 * ws)));
        const float4 hv = *(const float4*)(H + (size_t)row * DD + lane * 4);
        acc.x = fmaxf(acc.x, hv.x + e);
        acc.y = fmaxf(acc.y, hv.y + e);
        acc.z = fmaxf(acc.z, hv.z + e);
        acc.w = fmaxf(acc.w, hv.w + e);
    }

    *(float4*)(agg + (size_t)warp * DD + lane * 4) = acc;

    // block-level stats partials (deterministic order)
    sh_s[wloc][lane * 4 + 0] = acc.x;
    sh_s[wloc][lane * 4 + 1] = acc.y;
    sh_s[wloc][lane * 4 + 2] = acc.z;
    sh_s[wloc][lane * 4 + 3] = acc.w;
    sh_q[wloc][lane * 4 + 0] = acc.x * acc.x;
    sh_q[wloc][lane * 4 + 1] = acc.y * acc.y;
    sh_q[wloc][lane * 4 + 2] = acc.z * acc.z;
    sh_q[wloc][lane * 4 + 3] = acc.w * acc.w;
    __syncthreads();

    if (threadIdx.x < 128) {
        const int ch = threadIdx.x;
        float s = 0.f;
#pragma unroll
        for (int w = 0; w < 8; w++) s += sh_s[w][ch];
        g_psum[blockIdx.x][ch] = s;
    } else {
        const int ch = threadIdx.x - 128;
        float q = 0.f;
#pragma unroll
        for (int w = 0; w < 8; w++) q += sh_q[w][ch];
        g_psum2[blockIdx.x][ch] = q;
    }
}

// ---------------- kernel 3: stats finalize (one block per channel) --------
__global__ void __launch_bounds__(256) stats2_kernel(const float* __restrict__ bn_w,
                                                     const float* __restrict__ bn_b) {
    __shared__ float rs[256], rq[256];
    const int ch  = blockIdx.x;
    const int tid = threadIdx.x;

    float s = 0.f, q = 0.f;
    for (int p = tid; p < NPART; p += 256) {
        s += g_psum[p][ch];
        q += g_psum2[p][ch];
    }
    rs[tid] = s;
    rq[tid] = q;
    __syncthreads();
#pragma unroll
    for (int st = 128; st > 0; st >>= 1) {
        if (tid < st) {
            rs[tid] += rs[tid + st];
            rq[tid] += rq[tid + st];
        }
        __syncthreads();
    }
    if (tid == 0) {
        const float inv_m = 1.f / (float)MM;
        const float mean = rs[0] * inv_m;
        const float var  = fmaf(-mean, mean, rq[0] * inv_m);
        const float a = bn_w[ch] * rsqrtf(var + BN_EPS);
        g_scale[ch] = a;
        g_shift[ch] = fmaf(-mean, a, bn_b[ch]);
    }
}

// ---------------- kernel 4: in-place normalize ----------------------------
__global__ void __launch_bounds__(256) norm_kernel(float* __restrict__ out) {
    __shared__ float sa[DD], sb[DD];
    if (threadIdx.x < DD) {
        sa[threadIdx.x] = g_scale[threadIdx.x];
        sb[threadIdx.x] = g_shift[threadIdx.x];
    }
    __syncthreads();

    const int total = MM * (DD / 4);   // float4 elements
    for (int t = blockIdx.x * blockDim.x + threadIdx.x; t < total;
         t += gridDim.x * blockDim.x) {
        float4 v = ((float4*)out)[t];
        const int c0 = (t & 31) * 4;
        v.x = fmaf(v.x, sa[c0 + 0], sb[c0 + 0]);
        v.y = fmaf(v.y, sa[c0 + 1], sb[c0 + 1]);
        v.z = fmaf(v.z, sa[c0 + 2], sb[c0 + 2]);
        v.w = fmaf(v.w, sa[c0 + 3], sb[c0 + 3]);
        ((float4*)out)[t] = v;
    }
}

// ---------------- launch ---------------------------------------------------
extern "C" void kernel_launch(void* const* d_in, const int* in_sizes, int n_in,
                              void* d_out, int out_size) {
    const float* x      = (const float*)d_in[0];
    const float* xyz    = (const float*)d_in[1];
    const int*   knn    = (const int*)  d_in[2];
    const float* proj_w = (const float*)d_in[3];
    const float* coor   = (const float*)d_in[4];
    const float* scale  = (const float*)d_in[5];
    const float* bn_w   = (const float*)d_in[6];
    const float* bn_b   = (const float*)d_in[7];
    float* out = (float*)d_out;

    float* h;
    cudaGetSymbolAddress((void**)&h, g_h);

    gemm_kernel<<<MM / 128, 256>>>(x, proj_w, h);
    gather_kernel<<<MM / 8, 256>>>(h, xyz, knn, coor, scale, out);
    stats2_kernel<<<DD, 256>>>(bn_w, bn_b);
    norm_kernel<<<1024, 256>>>(out);
}

// round 4
// speedup vs baseline: 1.7947x; 1.2241x over previous
#include <cuda_runtime.h>
#include <cuda_fp16.h>
#include <cuda_bf16.h>
#include <cstdint>

#define BB 4
#define NN 8192
#define KK 16
#define DD 128
#define GG 32
#define MM (BB*NN)          // 32768 rows
#define BN_EPS 1e-5f

#define NPART 4096          // gather blocks = stats partials

// ---------------- scratch (device globals; no allocation) ----------------
__device__ __half g_h[(size_t)MM * DD];       // projected features, fp16, 8 MB
__device__ float g_psum [NPART][DD];          // per-gather-block partial sums
__device__ float g_psum2[NPART][DD];          // per-gather-block partial sumsq
__device__ float g_scale[DD];                 // fused BN scale
__device__ float g_shift[DD];                 // fused BN shift

// ---------------- mma / ldmatrix helpers ----------------------------------
#define LDSM4(r0, r1, r2, r3, addr)                                            \
    asm volatile("ldmatrix.sync.aligned.m8n8.x4.shared.b16 {%0,%1,%2,%3}, [%4];" \
                 : "=r"(r0), "=r"(r1), "=r"(r2), "=r"(r3) : "r"(addr))

__device__ __forceinline__ void mma_bf16(float c[4],
                                         uint32_t a0, uint32_t a1, uint32_t a2, uint32_t a3,
                                         uint32_t b0, uint32_t b1) {
    asm volatile(
        "mma.sync.aligned.m16n8k16.row.col.f32.bf16.bf16.f32 "
        "{%0,%1,%2,%3}, {%4,%5,%6,%7}, {%8,%9}, {%0,%1,%2,%3};"
        : "+f"(c[0]), "+f"(c[1]), "+f"(c[2]), "+f"(c[3])
        : "r"(a0), "r"(a1), "r"(a2), "r"(a3), "r"(b0), "r"(b1));
}

// ---------------- kernel 1: H = X * W^T, split-bf16 3-MMA -----------------
// Block 256 thr (8 warps: wm 0..3, wn 0..1). Tile M128 x N128, warp 32x64.
// K staged by 32 (2 k16 MMA steps per stage). Smem bf16 rows of 32 + 8 pad.
#define BK 32
#define RS 40   // smem row stride in bf16 elems (80 B -> LDSM conflict-free)
__global__ void __launch_bounds__(256) gemm_kernel(const float* __restrict__ X,
                                                   const float* __restrict__ W,
                                                   __half* __restrict__ H) {
    __shared__ __nv_bfloat16 Xhi[128 * RS];
    __shared__ __nv_bfloat16 Xlo[128 * RS];
    __shared__ __nv_bfloat16 Whi[128 * RS];
    __shared__ __nv_bfloat16 Wlo[128 * RS];

    const int tid  = threadIdx.x;
    const int warp = tid >> 5;
    const int lane = tid & 31;
    const int wm   = warp >> 1;          // 0..3 -> M offset wm*32
    const int wn   = warp & 1;           // 0..1 -> N offset wn*64
    const int m0   = blockIdx.x * 128;
    const int gr   = lane >> 2;          // groupID 0..7
    const int gc   = lane & 3;           // tig 0..3
    const int l16  = lane & 15;
    const int kh   = (lane >> 4) << 3;   // 0 or 8 (k half for ldmatrix)

    float c[2][8][4];
#pragma unroll
    for (int i = 0; i < 2; i++)
#pragma unroll
        for (int j = 0; j < 8; j++)
#pragma unroll
            for (int t = 0; t < 4; t++) c[i][j][t] = 0.f;

    const uint32_t xhi_b = (uint32_t)__cvta_generic_to_shared(Xhi);
    const uint32_t xlo_b = (uint32_t)__cvta_generic_to_shared(Xlo);
    const uint32_t whi_b = (uint32_t)__cvta_generic_to_shared(Whi);
    const uint32_t wlo_b = (uint32_t)__cvta_generic_to_shared(Wlo);

    for (int kc = 0; kc < DD; kc += BK) {
        // load + split: X tile 128x32 and W tile 128x32, 4 float4/thread each
#pragma unroll
        for (int i = 0; i < 4; i++) {
            const int q   = tid + i * 256;   // 0..1023
            const int row = q >> 3;          // 0..127
            const int cq  = q & 7;           // float4 index within 32 k's
            {
                float4 v = *(const float4*)(X + (size_t)(m0 + row) * DD + kc + cq * 4);
                __nv_bfloat16 hx = __float2bfloat16(v.x);
                __nv_bfloat16 hy = __float2bfloat16(v.y);
                __nv_bfloat16 hz = __float2bfloat16(v.z);
                __nv_bfloat16 hw = __float2bfloat16(v.w);
                __nv_bfloat162 hp0 = __halves2bfloat162(hx, hy);
                __nv_bfloat162 hp1 = __halves2bfloat162(hz, hw);
                __nv_bfloat162 lp0 = __halves2bfloat162(
                    __float2bfloat16(v.x - __bfloat162float(hx)),
                    __float2bfloat16(v.y - __bfloat162float(hy)));
                __nv_bfloat162 lp1 = __halves2bfloat162(
                    __float2bfloat16(v.z - __bfloat162float(hz)),
                    __float2bfloat16(v.w - __bfloat162float(hw)));
                *(uint2*)&Xhi[row * RS + cq * 4] =
                    make_uint2(*(uint32_t*)&hp0, *(uint32_t*)&hp1);
                *(uint2*)&Xlo[row * RS + cq * 4] =
                    make_uint2(*(uint32_t*)&lp0, *(uint32_t*)&lp1);
            }
            {
                float4 v = *(const float4*)(W + (size_t)row * DD + kc + cq * 4);
                __nv_bfloat16 hx = __float2bfloat16(v.x);
                __nv_bfloat16 hy = __float2bfloat16(v.y);
                __nv_bfloat16 hz = __float2bfloat16(v.z);
                __nv_bfloat16 hw = __float2bfloat16(v.w);
                __nv_bfloat162 hp0 = __halves2bfloat162(hx, hy);
                __nv_bfloat162 hp1 = __halves2bfloat162(hz, hw);
                __nv_bfloat162 lp0 = __halves2bfloat162(
                    __float2bfloat16(v.x - __bfloat162float(hx)),
                    __float2bfloat16(v.y - __bfloat162float(hy)));
                __nv_bfloat162 lp1 = __halves2bfloat162(
                    __float2bfloat16(v.z - __bfloat162float(hz)),
                    __float2bfloat16(v.w - __bfloat162float(hw)));
                *(uint2*)&Whi[row * RS + cq * 4] =
                    make_uint2(*(uint32_t*)&hp0, *(uint32_t*)&hp1);
                *(uint2*)&Wlo[row * RS + cq * 4] =
                    make_uint2(*(uint32_t*)&lp0, *(uint32_t*)&lp1);
            }
        }
        __syncthreads();

#pragma unroll
        for (int s = 0; s < BK / 16; s++) {
            const uint32_t koff = (kh + s * 16) * 2;   // byte offset of k half

            uint32_t ahi[2][4], alo[2][4];
#pragma unroll
            for (int am = 0; am < 2; am++) {
                const uint32_t ro = (uint32_t)(wm * 32 + am * 16 + l16) * (RS * 2) + koff;
                LDSM4(ahi[am][0], ahi[am][1], ahi[am][2], ahi[am][3], xhi_b + ro);
                LDSM4(alo[am][0], alo[am][1], alo[am][2], alo[am][3], xlo_b + ro);
            }
            uint32_t bhi[4][4], blo[4][4];   // [pair][b0_even,b0_odd,b1_even,b1_odd]
#pragma unroll
            for (int p = 0; p < 4; p++) {
                const uint32_t ro = (uint32_t)(wn * 64 + p * 16 + l16) * (RS * 2) + koff;
                LDSM4(bhi[p][0], bhi[p][1], bhi[p][2], bhi[p][3], whi_b + ro);
                LDSM4(blo[p][0], blo[p][1], blo[p][2], blo[p][3], wlo_b + ro);
            }

#pragma unroll
            for (int p = 0; p < 4; p++)
#pragma unroll
                for (int e = 0; e < 2; e++) {
                    const int an = 2 * p + e;
                    const uint32_t bh0 = bhi[p][e], bh1 = bhi[p][2 + e];
                    const uint32_t bl0 = blo[p][e], bl1 = blo[p][2 + e];
#pragma unroll
                    for (int am = 0; am < 2; am++) {
                        mma_bf16(c[am][an], ahi[am][0], ahi[am][1], ahi[am][2], ahi[am][3], bh0, bh1);
                        mma_bf16(c[am][an], ahi[am][0], ahi[am][1], ahi[am][2], ahi[am][3], bl0, bl1);
                        mma_bf16(c[am][an], alo[am][0], alo[am][1], alo[am][2], alo[am][3], bh0, bh1);
                    }
                }
        }
        __syncthreads();
    }

    // epilogue -> fp16 H
#pragma unroll
    for (int am = 0; am < 2; am++) {
        const int row = m0 + wm * 32 + am * 16 + gr;
#pragma unroll
        for (int an = 0; an < 8; an++) {
            const int col = wn * 64 + an * 8 + 2 * gc;
            *(__half2*)(H + (size_t)row * DD + col) =
                __floats2half2_rn(c[am][an][0], c[am][an][1]);
            *(__half2*)(H + (size_t)(row + 8) * DD + col) =
                __floats2half2_rn(c[am][an][2], c[am][an][3]);
        }
    }
}

// ---------------- kernel 2: gather + encoding + max + stats partials ------
// One warp per point, 8 points/block. Lane g owns channels [4g,4g+4).
__global__ void __launch_bounds__(256) gather_kernel(const __half* __restrict__ H,
                                                     const float* __restrict__ xyz,
                                                     const int* __restrict__ knn,
                                                     const float* __restrict__ coor,
                                                     const float* __restrict__ scale,
                                                     float* __restrict__ agg) {
    __shared__ float sh_s[8][132];
    __shared__ float sh_q[8][132];

    const int warp = (blockIdx.x * blockDim.x + threadIdx.x) >> 5;
    const int wloc = threadIdx.x >> 5;
    const int lane = threadIdx.x & 31;

    const int b = warp >> 13;          // warp / 8192
    const int base = b << 13;          // b*N

    const float wx = coor[3 * lane + 0];
    const float wy = coor[3 * lane + 1];
    const float wz = coor[3 * lane + 2];
    const float sv = scale[lane];
    const float ws = sv * sv;

    const float* cptr = xyz + (size_t)warp * 3;
    const float cx = cptr[0], cy = cptr[1], cz = cptr[2];

    const int nb = knn[(size_t)warp * KK + (lane & 15)];

    float4 acc = make_float4(-3.402823466e38f, -3.402823466e38f,
                             -3.402823466e38f, -3.402823466e38f);

#pragma unroll
    for (int k = 0; k < KK; k++) {
        const int idx = __shfl_sync(0xffffffffu, nb, k);
        const int row = base + idx;
        const float* nx = xyz + (size_t)row * 3;
        const float rx = nx[0] - cx;
        const float ry = nx[1] - cy;
        const float rz = nx[2] - cz;
        const float r2 = fmaf(rx, rx, fmaf(ry, ry, rz * rz));
        const float e  = fmaf(rx, wx, fmaf(ry, wy, fmaf(rz, wz, r2 * ws)));
        const uint2 hv = *(const uint2*)(H + (size_t)row * DD + lane * 4);
        const float2 f0 = __half22float2(*(const __half2*)&hv.x);
        const float2 f1 = __half22float2(*(const __half2*)&hv.y);
        acc.x = fmaxf(acc.x, f0.x + e);
        acc.y = fmaxf(acc.y, f0.y + e);
        acc.z = fmaxf(acc.z, f1.x + e);
        acc.w = fmaxf(acc.w, f1.y + e);
    }

    *(float4*)(agg + (size_t)warp * DD + lane * 4) = acc;

    // block-level stats partials (deterministic order)
    sh_s[wloc][lane * 4 + 0] = acc.x;
    sh_s[wloc][lane * 4 + 1] = acc.y;
    sh_s[wloc][lane * 4 + 2] = acc.z;
    sh_s[wloc][lane * 4 + 3] = acc.w;
    sh_q[wloc][lane * 4 + 0] = acc.x * acc.x;
    sh_q[wloc][lane * 4 + 1] = acc.y * acc.y;
    sh_q[wloc][lane * 4 + 2] = acc.z * acc.z;
    sh_q[wloc][lane * 4 + 3] = acc.w * acc.w;
    __syncthreads();

    if (threadIdx.x < 128) {
        const int ch = threadIdx.x;
        float s = 0.f;
#pragma unroll
        for (int w = 0; w < 8; w++) s += sh_s[w][ch];
        g_psum[blockIdx.x][ch] = s;
    } else {
        const int ch = threadIdx.x - 128;
        float q = 0.f;
#pragma unroll
        for (int w = 0; w < 8; w++) q += sh_q[w][ch];
        g_psum2[blockIdx.x][ch] = q;
    }
}

// ---------------- kernel 3: stats finalize (one block per channel) --------
__global__ void __launch_bounds__(256) stats2_kernel(const float* __restrict__ bn_w,
                                                     const float* __restrict__ bn_b) {
    __shared__ float rs[256], rq[256];
    const int ch  = blockIdx.x;
    const int tid = threadIdx.x;

    float s = 0.f, q = 0.f;
    for (int p = tid; p < NPART; p += 256) {
        s += g_psum[p][ch];
        q += g_psum2[p][ch];
    }
    rs[tid] = s;
    rq[tid] = q;
    __syncthreads();
#pragma unroll
    for (int st = 128; st > 0; st >>= 1) {
        if (tid < st) {
            rs[tid] += rs[tid + st];
            rq[tid] += rq[tid + st];
        }
        __syncthreads();
    }
    if (tid == 0) {
        const float inv_m = 1.f / (float)MM;
        const float mean = rs[0] * inv_m;
        const float var  = fmaf(-mean, mean, rq[0] * inv_m);
        const float a = bn_w[ch] * rsqrtf(var + BN_EPS);
        g_scale[ch] = a;
        g_shift[ch] = fmaf(-mean, a, bn_b[ch]);
    }
}

// ---------------- kernel 4: in-place normalize ----------------------------
__global__ void __launch_bounds__(256) norm_kernel(float* __restrict__ out) {
    __shared__ float sa[DD], sb[DD];
    if (threadIdx.x < DD) {
        sa[threadIdx.x] = g_scale[threadIdx.x];
        sb[threadIdx.x] = g_shift[threadIdx.x];
    }
    __syncthreads();

    const int total = MM * (DD / 4);   // float4 elements
    for (int t = blockIdx.x * blockDim.x + threadIdx.x; t < total;
         t += gridDim.x * blockDim.x) {
        float4 v = ((float4*)out)[t];
        const int c0 = (t & 31) * 4;
        v.x = fmaf(v.x, sa[c0 + 0], sb[c0 + 0]);
        v.y = fmaf(v.y, sa[c0 + 1], sb[c0 + 1]);
        v.z = fmaf(v.z, sa[c0 + 2], sb[c0 + 2]);
        v.w = fmaf(v.w, sa[c0 + 3], sb[c0 + 3]);
        ((float4*)out)[t] = v;
    }
}

// ---------------- launch ---------------------------------------------------
extern "C" void kernel_launch(void* const* d_in, const int* in_sizes, int n_in,
                              void* d_out, int out_size) {
    const float* x      = (const float*)d_in[0];
    const float* xyz    = (const float*)d_in[1];
    const int*   knn    = (const int*)  d_in[2];
    const float* proj_w = (const float*)d_in[3];
    const float* coor   = (const float*)d_in[4];
    const float* scale  = (const float*)d_in[5];
    const float* bn_w   = (const float*)d_in[6];
    const float* bn_b   = (const float*)d_in[7];
    float* out = (float*)d_out;

    __half* h;
    cudaGetSymbolAddress((void**)&h, g_h);

    gemm_kernel<<<MM / 128, 256>>>(x, proj_w, h);
    gather_kernel<<<MM / 8, 256>>>(h, xyz, knn, coor, scale, out);
    stats2_kernel<<<DD, 256>>>(bn_w, bn_b);
    norm_kernel<<<1024, 256>>>(out);
}